// round 16
// baseline (speedup 1.0000x reference)
#include <cuda_runtime.h>

#define SEQ     2048
#define HEADS   8
#define MI      2
#define SLOTS   64
#define JG      16
#define NTHREADS 1024              // SLOTS * JG
#define JPAIRS  (SEQ / 2)          // 1024 packed j-pairs
#define NC      148                // grid: 4 heads x 19 CTAs + 4 heads x 18 CTAs

using u64 = unsigned long long;

__device__ __forceinline__ float ex2f(float x) {
    float y;
    asm("ex2.approx.f32 %0, %1;" : "=f"(y) : "f"(x));
    return y;
}
__device__ __forceinline__ u64 pack2(float lo, float hi) {
    u64 r; asm("mov.b64 %0, {%1, %2};" : "=l"(r) : "f"(lo), "f"(hi)); return r;
}
__device__ __forceinline__ void unpack2(u64 v, float& lo, float& hi) {
    asm("mov.b64 {%0, %1}, %2;" : "=f"(lo), "=f"(hi) : "l"(v));
}
__device__ __forceinline__ u64 fma2(u64 a, u64 b, u64 c) {
    u64 d; asm("fma.rn.f32x2 %0, %1, %2, %3;" : "=l"(d) : "l"(a), "l"(b), "l"(c)); return d;
}
__device__ __forceinline__ u64 mul2(u64 a, u64 b) {
    u64 d; asm("mul.rn.f32x2 %0, %1, %2;" : "=l"(d) : "l"(a), "l"(b)); return d;
}
__device__ __forceinline__ u64 add2(u64 a, u64 b) {
    u64 d; asm("add.rn.f32x2 %0, %1, %2;" : "=l"(d) : "l"(a), "l"(b)); return d;
}
__device__ __forceinline__ u64 ex2_2(u64 s) {
    float lo, hi; unpack2(s, lo, hi);
    return pack2(ex2f(lo), ex2f(hi));
}

// Interleaved, j-pair packed smem: one 16B word holds two components for a
// j-pair -> 3 x LDS.128 per iteration (was 6 x LDS.64 + 6 address chains).
// s_k1[jp] = {kx0,kx1, ky0,ky1}   (normalized key, comps 0,1)
// s_k2[jp] = {kz0,kz1, kw0,kw1}   (normalized key, comps 2,3)
// s_v [jp] = {v00,v01, v10,v11}   (RAW real parts = unnormalized V)
// 3 * 16KB = 48KB static smem.
__shared__ ulonglong2 s_k1[JPAIRS];
__shared__ ulonglong2 s_k2[JPAIRS];
__shared__ ulonglong2 s_v [JPAIRS];

__global__ __launch_bounds__(NTHREADS, 1)
void su2_attn_kernel(const float* __restrict__ re,
                     const float* __restrict__ im,
                     float* __restrict__ out) {
    const int cta = blockIdx.x;
    // Head-aligned 148-way split: heads 0..3 get 19 CTAs, heads 4..7 get 18.
    int h, r, P;
    if (cta < 76) { h = cta / 19;       r = cta - h * 19;      P = 19; }
    else          { h = 4 + (cta - 76) / 18; r = (cta - 76) - (h - 4) * 18; P = 18; }
    const int i_lo = (r * SEQ) / P;
    const int i_hi = ((r + 1) * SEQ) / P;
    const int nq   = i_hi - i_lo;           // 107..114 (<= 128 capacity)

    const int tid = threadIdx.x;
    float* k1f = reinterpret_cast<float*>(s_k1);
    float* k2f = reinterpret_cast<float*>(s_k2);
    float* vf  = reinterpret_cast<float*>(s_v);

    // Phase 1: normalize all 2048 keys of this head into interleaved smem.
    #pragma unroll
    for (int j = tid; j < SEQ; j += NTHREADS) {
        const int base = j * (HEADS * 2) + h * 2;
        const float2 rr = *reinterpret_cast<const float2*>(re + base);
        const float2 mm = *reinterpret_cast<const float2*>(im + base);
        const float ss  = rr.x * rr.x + rr.y * rr.y + mm.x * mm.x + mm.y * mm.y;
        const float rin = rsqrtf(ss);
        const int jp = j >> 1, lo = j & 1;
        k1f[jp * 4 + lo]     = rr.x * rin;
        k1f[jp * 4 + 2 + lo] = rr.y * rin;
        k2f[jp * 4 + lo]     = mm.x * rin;
        k2f[jp * 4 + 2 + lo] = mm.y * rin;
        vf [jp * 4 + lo]     = rr.x;        // raw = unnormalized V comp 0
        vf [jp * 4 + 2 + lo] = rr.y;        // raw = unnormalized V comp 1
    }
    __syncthreads();

    const int slot = tid >> 4;              // 0..63
    const int jg   = tid & 15;              // 0..15 (16-lane group in warp)
    const unsigned gmask = 0xFFFFu << ((tid & 31) & 16);  // this slot's lanes

    const bool full2 = (slot + SLOTS) < nq; // second query slot valid?
    const int i0 = i_lo + slot;             // always valid (nq >= 107 > 63)

    // exp(dot * SCALE) == ex2(dot * SCALE*log2(e)); logits bounded by unit
    // vectors -> no max subtraction needed in softmax.
    const float C = 0.70710678118654752f * 1.44269504088896341f;

    u64 qx0, qy0, qz0, qw0, qx1 = 0, qy1 = 0, qz1 = 0, qw1 = 0;
    {
        const int e = (i0 >> 1) * 4 + (i0 & 1);
        float vx = k1f[e] * C, vy = k1f[e + 2] * C;
        float vz = k2f[e] * C, vw = k2f[e + 2] * C;
        qx0 = pack2(vx, vx); qy0 = pack2(vy, vy);
        qz0 = pack2(vz, vz); qw0 = pack2(vw, vw);
    }
    if (full2) {
        const int i1 = i0 + SLOTS;
        const int e = (i1 >> 1) * 4 + (i1 & 1);
        float vx = k1f[e] * C, vy = k1f[e + 2] * C;
        float vz = k2f[e] * C, vw = k2f[e + 2] * C;
        qx1 = pack2(vx, vx); qy1 = pack2(vy, vy);
        qz1 = pack2(vz, vz); qw1 = pack2(vw, vw);
    }

    u64 l0 = 0, x0 = 0, y0 = 0, l1 = 0, x1 = 0, y1 = 0;

    if (full2) {
        #pragma unroll 4
        for (int jp = jg; jp < JPAIRS; jp += JG) {
            const ulonglong2 A = s_k1[jp];
            const ulonglong2 B = s_k2[jp];
            const ulonglong2 V = s_v [jp];
            // q0
            u64 s = mul2(qw0, B.y);
            s = fma2(qz0, B.x, s);
            s = fma2(qy0, A.y, s);
            s = fma2(qx0, A.x, s);
            u64 p = ex2_2(s);
            l0 = add2(l0, p);
            x0 = fma2(p, V.x, x0);
            y0 = fma2(p, V.y, y0);
            // q1
            s = mul2(qw1, B.y);
            s = fma2(qz1, B.x, s);
            s = fma2(qy1, A.y, s);
            s = fma2(qx1, A.x, s);
            p = ex2_2(s);
            l1 = add2(l1, p);
            x1 = fma2(p, V.x, x1);
            y1 = fma2(p, V.y, y1);
        }
    } else {
        #pragma unroll 4
        for (int jp = jg; jp < JPAIRS; jp += JG) {
            const ulonglong2 A = s_k1[jp];
            const ulonglong2 B = s_k2[jp];
            const ulonglong2 V = s_v [jp];
            u64 s = mul2(qw0, B.y);
            s = fma2(qz0, B.x, s);
            s = fma2(qy0, A.y, s);
            s = fma2(qx0, A.x, s);
            const u64 p = ex2_2(s);
            l0 = add2(l0, p);
            x0 = fma2(p, V.x, x0);
            y0 = fma2(p, V.y, y0);
        }
    }

    // q0 reduce + store (group-local butterfly over the 16 jg lanes).
    {
        float la, lb, xa, xb, ya, yb;
        unpack2(l0, la, lb); unpack2(x0, xa, xb); unpack2(y0, ya, yb);
        float l = la + lb, x = xa + xb, y = ya + yb;
        #pragma unroll
        for (int m = 1; m <= 8; m <<= 1) {
            l += __shfl_xor_sync(gmask, l, m);
            x += __shfl_xor_sync(gmask, x, m);
            y += __shfl_xor_sync(gmask, y, m);
        }
        if (jg == 0) {
            const float inv = 1.0f / l;
            reinterpret_cast<float2*>(out)[i0 * HEADS + h] =
                make_float2(x * inv, y * inv);
        }
    }
    // q1 reduce + store.
    if (full2) {
        float la, lb, xa, xb, ya, yb;
        unpack2(l1, la, lb); unpack2(x1, xa, xb); unpack2(y1, ya, yb);
        float l = la + lb, x = xa + xb, y = ya + yb;
        #pragma unroll
        for (int m = 1; m <= 8; m <<= 1) {
            l += __shfl_xor_sync(gmask, l, m);
            x += __shfl_xor_sync(gmask, x, m);
            y += __shfl_xor_sync(gmask, y, m);
        }
        if (jg == 0) {
            const float inv = 1.0f / l;
            reinterpret_cast<float2*>(out)[(i0 + SLOTS) * HEADS + h] =
                make_float2(x * inv, y * inv);
        }
    }
}

extern "C" void kernel_launch(void* const* d_in, const int* in_sizes, int n_in,
                              void* d_out, int out_size) {
    const float* re = (const float*)d_in[0];
    const float* im = (const float*)d_in[1];
    float* out = (float*)d_out;

    su2_attn_kernel<<<NC, NTHREADS>>>(re, im, out);
}